// round 4
// baseline (speedup 1.0000x reference)
#include <cuda_runtime.h>
#include <cstdint>

typedef unsigned long long ull;
#define NROWS 8192
#define NHID  64
#define NEMB  256

__device__ float  g_h[NROWS * NHID];
__device__ float2 g_fsp[NROWS];   // (f_src+b, exp(f_src+b))
__device__ float2 g_fdp[NROWS];   // (f_dst,   exp(f_dst))
__device__ int    g_cnt[NROWS];
__device__ int    g_R[NROWS];
__device__ uint4  g_bits4[NROWS * 64];  // bitmask: word q of chunk ch, bit l = adj[row][128*ch+32*q+l]

__device__ __forceinline__ ull packf2(float lo, float hi) {
    ull r;
    asm("mov.b64 %0, {%1, %2};" : "=l"(r) : "r"(__float_as_uint(lo)), "r"(__float_as_uint(hi)));
    return r;
}
__device__ __forceinline__ void unpackf2(float& lo, float& hi, ull v) {
    unsigned a, b;
    asm("mov.b64 {%0, %1}, %2;" : "=r"(a), "=r"(b) : "l"(v));
    lo = __uint_as_float(a); hi = __uint_as_float(b);
}
__device__ __forceinline__ void fma2(ull& d, ull a, ull b) {
    asm("fma.rn.f32x2 %0, %1, %2, %0;" : "+l"(d) : "l"(a), "l"(b));
}
__device__ __forceinline__ ull addf2(ull a, ull b) {
    ull d; asm("add.rn.f32x2 %0, %1, %2;" : "=l"(d) : "l"(a), "l"(b)); return d;
}

// ======================= K1: h, f_src, f_dst, exp tables =======================
__global__ void k_h(const float* __restrict__ x, const float* __restrict__ Ww,
                    const float* __restrict__ Wb, const float* __restrict__ a1,
                    const float* __restrict__ a2, const float* __restrict__ ab) {
    __shared__ float xs[4][NEMB];
    __shared__ float s1[4][2], s2[4][2];
    const int tid = threadIdx.x;
    const int r = tid >> 6, d = tid & 63;
    const int row = blockIdx.x * 4 + r;

    ((float4*)&xs[0][0])[tid] = ((const float4*)(x + (size_t)blockIdx.x * 4 * NEMB))[tid];
    __syncthreads();

    float acc = Wb[d];
    #pragma unroll 8
    for (int k = 0; k < NEMB; k++)
        acc = fmaf(xs[r][k], __ldg(Ww + k * NHID + d), acc);
    g_h[(size_t)row * NHID + d] = acc;

    float v1 = acc * __ldg(a1 + d);
    float v2 = acc * __ldg(a2 + d);
    #pragma unroll
    for (int o = 16; o >= 1; o >>= 1) {
        v1 += __shfl_xor_sync(0xffffffffu, v1, o);
        v2 += __shfl_xor_sync(0xffffffffu, v2, o);
    }
    const int half = (tid >> 5) & 1;
    if ((tid & 31) == 0) { s1[r][half] = v1; s2[r][half] = v2; }
    __syncthreads();
    if (d == 0) {
        float fs = s1[r][0] + s1[r][1] + ab[0];
        float fd = s2[r][0] + s2[r][1];
        g_fsp[row] = make_float2(fs, expf(fs));
        g_fdp[row] = make_float2(fd, expf(fd));
    }
}

// ======================= K2: bitmask build + per-row counts =======================
__global__ void k_mask(const int* __restrict__ adj) {
    const int w = threadIdx.x >> 5, lane = threadIdx.x & 31;
    const int row = blockIdx.x * 8 + w;
    const int* p = adj + (size_t)row * NROWS;
    int c = 0;
    #pragma unroll 4
    for (int ch = 0; ch < 64; ch++) {
        const int* q = p + ch * 128 + lane;
        unsigned W0 = __ballot_sync(0xffffffffu, __ldg(q)      > 0);
        unsigned W1 = __ballot_sync(0xffffffffu, __ldg(q + 32) > 0);
        unsigned W2 = __ballot_sync(0xffffffffu, __ldg(q + 64) > 0);
        unsigned W3 = __ballot_sync(0xffffffffu, __ldg(q + 96) > 0);
        if (lane == 0) g_bits4[row * 64 + ch] = make_uint4(W0, W1, W2, W3);
        c += __popc(W0) + __popc(W1) + __popc(W2) + __popc(W3);
    }
    if (lane == 0) g_cnt[row] = c;
}

// ======================= K3: exclusive scan of counts =======================
__global__ void k_scan() {
    __shared__ int sums[256];
    const int t = threadIdx.x;
    const int base = t * 32;
    int tot = 0;
    #pragma unroll
    for (int k = 0; k < 32; k++) tot += g_cnt[base + k];
    sums[t] = tot;
    __syncthreads();
    #pragma unroll
    for (int off = 1; off < 256; off <<= 1) {
        int u = (t >= off) ? sums[t - off] : 0;
        __syncthreads();
        sums[t] += u;
        __syncthreads();
    }
    int run = sums[t] - tot;
    #pragma unroll
    for (int k = 0; k < 32; k++) { int c = g_cnt[base + k]; g_R[base + k] = run; run += c; }
}

// ======================= K4: main fused kernel =======================
__device__ __forceinline__ float edgeE(int rr) {
    float2 a  = __ldg(&g_fsp[rr >> 13]);
    float2 bq = __ldg(&g_fdp[rr & (NROWS - 1)]);
    float s = a.x + bq.x;
    float u = 0.01f * s;   // leaky slope branch: exp(u), u in (-0.05, 0]
    float p = fmaf(u, 0.0416666679f, 0.1666666716f);
    p = fmaf(p, u, 0.5f);
    p = fmaf(p, u, 1.0f);
    p = fmaf(p, u, 1.0f);
    return (s >= 0.0f) ? a.y * bq.y : p;
}

__device__ __forceinline__ void red_store(ull (&acc)[8][4], ull* redu, int slotbase) {
    #pragma unroll
    for (int k = 0; k < 8; k++)
        #pragma unroll
        for (int p = 0; p < 4; p++)
            redu[slotbase + (k * 4 + p) * 32] = acc[k][p];
}
__device__ __forceinline__ void red_add(ull (&acc)[8][4], const ull* redu, int slotbase) {
    #pragma unroll
    for (int k = 0; k < 8; k++)
        #pragma unroll
        for (int p = 0; p < 4; p++)
            acc[k][p] = addf2(acc[k][p], redu[slotbase + (k * 4 + p) * 32]);
}

// smem: Wt [128][32] rotated (4096 f) | hs [128][64] (8192 f) ; sS overlaid at +12256
__global__ void __launch_bounds__(256, 2)
k_main(float* __restrict__ out) {
    __shared__ float sm[12288];
    float* Wt = sm;                // 4096 floats: Wt[j*32 + ((il + j) & 31)] = W[il][j]
    float* hs = sm + 4096;         // 8192 floats
    float* sS = sm + 12256;        // 32 floats (tail of hs, written only at end)

    const int tid  = threadIdx.x;
    const int w    = tid >> 5;
    const int lane = tid & 31;
    const int rg   = lane >> 3;    // 0..3 -> rows 8rg..8rg+7
    const int dg   = lane & 7;     // dims 4dg..4dg+3 and 32+4dg..+3
    const int row0 = blockIdx.x * 32;
    const unsigned ml = (1u << lane) - 1u;  // lanemask_lt

    int   rank[4];
    float sacc[4];
    #pragma unroll
    for (int k = 0; k < 4; k++) { rank[k] = g_R[row0 + 4 * w + k]; sacc[k] = 0.0f; }

    ull acc[8][4];
    #pragma unroll
    for (int k = 0; k < 8; k++)
        #pragma unroll
        for (int p = 0; p < 4; p++) acc[k][p] = 0ull;

    for (int tile = 0; tile < 64; tile++) {     // 64 tiles x 128 cols = full N
        // ---- load h tile [128][64]
        {
            const float4* hsrc = (const float4*)g_h + (size_t)tile * 2048;
            #pragma unroll
            for (int t = 0; t < 8; t++)
                ((float4*)hs)[tid + t * 256] = __ldg(hsrc + tid + t * 256);
        }

        // ---- Phase A: dense rotated W tile + running ranks + row sums
        #pragma unroll
        for (int k = 0; k < 4; k++) {
            const int il = 4 * w + k;
            uint4 bw = __ldg(g_bits4 + (size_t)(row0 + il) * 64 + tile);
            const int P0 = __popc(bw.x), P1 = __popc(bw.y), P2 = __popc(bw.z), P3 = __popc(bw.w);
            const int r0 = rank[k] + __popc(bw.x & ml);
            const int r1 = rank[k] + P0 + __popc(bw.y & ml);
            const int r2 = rank[k] + P0 + P1 + __popc(bw.z & ml);
            const int r3 = rank[k] + P0 + P1 + P2 + __popc(bw.w & ml);
            rank[k] += P0 + P1 + P2 + P3;
            float w0 = 0.f, w1 = 0.f, w2 = 0.f, w3 = 0.f, sl = 0.f;
            if ((bw.x >> lane) & 1) { w0 = edgeE(r0); sl += w0; }
            if ((bw.y >> lane) & 1) { w1 = edgeE(r1); sl += w1; }
            if ((bw.z >> lane) & 1) { w2 = edgeE(r2); sl += w2; }
            if ((bw.w >> lane) & 1) { w3 = edgeE(r3); sl += w3; }
            // column c = 32q + lane ; addr = c*32 + ((il + lane) & 31)
            const int sbase = 32 * lane + ((il + lane) & 31);
            Wt[sbase]        = w0;
            Wt[sbase + 1024] = w1;
            Wt[sbase + 2048] = w2;
            Wt[sbase + 3072] = w3;
            sacc[k] += sl;
        }
        __syncthreads();

        // ---- Phase B: out(32x64) += W(32x128) @ h(128x64), FFMA2, j-phased by warp
        #pragma unroll 4
        for (int t = 0; t < 16; t++) {
            const int j = w + 8 * t;
            const int jb = j * 32;
            const int v0 = 8 * rg + j;
            float wr[8];
            #pragma unroll
            for (int k = 0; k < 8; k++)
                wr[k] = Wt[jb + ((v0 + k) & 31)];
            const float* hp = hs + j * 64;
            float4 ha = *(const float4*)(hp + dg * 4);
            float4 hb = *(const float4*)(hp + 32 + dg * 4);
            ull h2[4];
            h2[0] = packf2(ha.x, ha.y); h2[1] = packf2(ha.z, ha.w);
            h2[2] = packf2(hb.x, hb.y); h2[3] = packf2(hb.z, hb.w);
            #pragma unroll
            for (int k = 0; k < 8; k++) {
                ull wp2 = packf2(wr[k], wr[k]);
                fma2(acc[k][0], wp2, h2[0]);
                fma2(acc[k][1], wp2, h2[1]);
                fma2(acc[k][2], wp2, h2[2]);
                fma2(acc[k][3], wp2, h2[3]);
            }
        }
        __syncthreads();
    }

    // ---- per-row softmax denominators
    #pragma unroll
    for (int k = 0; k < 4; k++) {
        float sv = sacc[k];
        #pragma unroll
        for (int o = 16; o >= 1; o >>= 1) sv += __shfl_xor_sync(0xffffffffu, sv, o);
        if (lane == 0) sS[4 * w + k] = sv;
    }
    __syncthreads();

    // ---- tree-reduce the 8 j-phase partials (constant-index, stays in regs)
    ull* redu = (ull*)sm;   // uses float region [0, 8192) only
    if (w >= 4) red_store(acc, redu, (w - 4) * 1024 + lane);
    __syncthreads();
    if (w < 4)  red_add(acc, redu, w * 1024 + lane);
    __syncthreads();
    if (w == 2 || w == 3) red_store(acc, redu, (w - 2) * 1024 + lane);
    __syncthreads();
    if (w < 2)  red_add(acc, redu, w * 1024 + lane);
    __syncthreads();
    if (w == 1) red_store(acc, redu, lane);
    __syncthreads();

    if (w == 0) {
        red_add(acc, redu, lane);
        #pragma unroll
        for (int k = 0; k < 8; k++) {
            const int row = 8 * rg + k;
            const float sinv = 1.0f / sS[row];
            float v[8];
            unpackf2(v[0], v[1], acc[k][0]);
            unpackf2(v[2], v[3], acc[k][1]);
            unpackf2(v[4], v[5], acc[k][2]);
            unpackf2(v[6], v[7], acc[k][3]);
            float o[8];
            #pragma unroll
            for (int c = 0; c < 8; c++) {
                float t = v[c] * sinv;
                o[c] = (t > 0.0f) ? t : expm1f(t);
            }
            float* op = out + (size_t)(row0 + row) * NHID;
            *(float4*)(op + dg * 4)      = make_float4(o[0], o[1], o[2], o[3]);
            *(float4*)(op + 32 + dg * 4) = make_float4(o[4], o[5], o[6], o[7]);
        }
    }
}

extern "C" void kernel_launch(void* const* d_in, const int* in_sizes, int n_in,
                              void* d_out, int out_size) {
    (void)in_sizes; (void)n_in; (void)out_size;
    const float* x   = (const float*)d_in[0];
    const int*   adj = (const int*)d_in[1];
    const float* Ww  = (const float*)d_in[2];
    const float* Wb  = (const float*)d_in[3];
    const float* a1  = (const float*)d_in[4];
    const float* a2  = (const float*)d_in[5];
    const float* ab  = (const float*)d_in[6];
    float* out = (float*)d_out;

    k_h   <<<NROWS / 4, 256>>>(x, Ww, Wb, a1, a2, ab);
    k_mask<<<NROWS / 8, 256>>>(adj);
    k_scan<<<1, 256>>>();
    k_main<<<NROWS / 32, 256>>>(out);
}